// round 17
// baseline (speedup 1.0000x reference)
#include <cuda_runtime.h>
#include <cuda_fp16.h>
#include <math.h>
#include <stdint.h>

// Problem dims
#define B_   2
#define T_   1024
#define D_   1024
#define DI_  2048          // D_INNER
#define DS_  16            // D_STATE
#define R_   64            // DT_RANK
#define XDBC_ 96           // R_ + 2*DS_
#define MROWS (B_*T_)      // 2048

// ---------------------------------------------------------------------------
// Scratch (device globals; no allocation allowed)
// ---------------------------------------------------------------------------
__device__ __align__(256) float g_xz[MROWS * 2 * DI_];     // in_proj out (f32)
__device__ __align__(256) float g_u[MROWS * DI_];          // conv out f32 (scan)
__device__ __align__(256) float g_xdbc[MROWS * XDBC_];     // x_proj out (f32)
__device__ __align__(256) float g_delta[MROWS * DI_];      // dt_proj out (f32)

__device__ __align__(256) __half g_xnh[MROWS * D_];        // rmsnorm out
__device__ __align__(256) __half g_uh[MROWS * DI_];        // conv out (GEMM input)
__device__ __align__(256) __half g_yh[MROWS * DI_];        // scan out
__device__ __align__(256) __half g_xdbch[MROWS * XDBC_];   // xdbc (dt_proj input)
__device__ __align__(256) __half g_winh[2 * DI_ * D_];
__device__ __align__(256) __half g_wouth[D_ * DI_];
__device__ __align__(256) __half g_wxph[XDBC_ * DI_];
__device__ __align__(256) __half g_wdth[DI_ * R_];

// ---------------------------------------------------------------------------
// Helpers
// ---------------------------------------------------------------------------
__device__ __forceinline__ uint32_t smem_u32(const void* p) {
    uint32_t a;
    asm("{ .reg .u64 t; cvta.to.shared.u64 t, %1; cvt.u32.u64 %0, t; }" : "=r"(a) : "l"(p));
    return a;
}
__device__ __forceinline__ uint32_t sw128(uint32_t b) { return b ^ ((b >> 3) & 0x70); }

__device__ __forceinline__ void cp16(uint32_t smem, const void* gmem, int srcBytes) {
    asm volatile("cp.async.cg.shared.global [%0], [%1], 16, %2;"
                 :: "r"(smem), "l"(gmem), "r"(srcBytes));
}
__device__ __forceinline__ void cp_commit() {
    asm volatile("cp.async.commit_group;" ::: "memory");
}
template<int N>
__device__ __forceinline__ void cp_wait() {
    asm volatile("cp.async.wait_group %0;" :: "n"(N) : "memory");
}

__device__ __forceinline__ void ldsm_x4(uint32_t* r, uint32_t addr) {
    asm volatile("ldmatrix.sync.aligned.m8n8.x4.shared.b16 {%0,%1,%2,%3}, [%4];"
                 : "=r"(r[0]), "=r"(r[1]), "=r"(r[2]), "=r"(r[3]) : "r"(addr));
}
// fp16 m16n8k16 MMA, f32 accumulate
__device__ __forceinline__ void mma_fp16(float* c, const uint32_t* a, const uint32_t* b) {
    asm volatile("mma.sync.aligned.m16n8k16.row.col.f32.f16.f16.f32 "
                 "{%0,%1,%2,%3}, {%4,%5,%6,%7}, {%8,%9}, {%0,%1,%2,%3};"
                 : "+f"(c[0]), "+f"(c[1]), "+f"(c[2]), "+f"(c[3])
                 : "r"(a[0]), "r"(a[1]), "r"(a[2]), "r"(a[3]), "r"(b[0]), "r"(b[1]));
}

// pack 4 f32 -> 4 fp16 (uint2)
__device__ __forceinline__ uint2 h4(float4 v) {
    __half2 a = __floats2half2_rn(v.x, v.y);
    __half2 b = __floats2half2_rn(v.z, v.w);
    return make_uint2(*(uint32_t*)&a, *(uint32_t*)&b);
}

// ---------------------------------------------------------------------------
// Convert all weights to fp16 (fused, float4-vectorized)
// ---------------------------------------------------------------------------
#define S0_ (2 * DI_ * D_ / 4)
#define S1_ (D_ * DI_ / 4)
#define S2_ (XDBC_ * DI_ / 4)
#define S3_ (DI_ * R_ / 4)

__global__ void cvt_weights_kernel(
    const float* __restrict__ w0, __half* __restrict__ o0,
    const float* __restrict__ w1, __half* __restrict__ o1,
    const float* __restrict__ w2, __half* __restrict__ o2,
    const float* __restrict__ w3, __half* __restrict__ o3)
{
    int i = blockIdx.x * blockDim.x + threadIdx.x;
    const float* src; __half* dst; int off;
    if (i < S0_)                        { src = w0; dst = o0; off = i; }
    else if (i < S0_ + S1_)             { src = w1; dst = o1; off = i - S0_; }
    else if (i < S0_ + S1_ + S2_)       { src = w2; dst = o2; off = i - S0_ - S1_; }
    else if (i < S0_ + S1_ + S2_ + S3_) { src = w3; dst = o3; off = i - S0_ - S1_ - S2_; }
    else return;
    ((uint2*)dst)[off] = h4(((const float4*)src)[off]);
}

__global__ void cvt_kernel(const float* __restrict__ src, __half* __restrict__ dst, int n4)
{
    int i = blockIdx.x * blockDim.x + threadIdx.x;
    if (i < n4) ((uint2*)dst)[i] = h4(((const float4*)src)[i]);
}

__global__ void copy_kernel(const float* __restrict__ src, float* __restrict__ dst, int n4)
{
    int i = blockIdx.x * blockDim.x + threadIdx.x;
    if (i < n4) ((float4*)dst)[i] = ((const float4*)src)[i];
}

// ---------------------------------------------------------------------------
// RMSNorm -> fp16
// ---------------------------------------------------------------------------
__global__ void rmsnorm_kernel(const float* __restrict__ x,
                               const float* __restrict__ w,
                               __half* __restrict__ o)
{
    int row = blockIdx.x;
    const float* xr = x + (size_t)row * D_;
    float s = 0.f;
    for (int i = threadIdx.x; i < D_ / 4; i += 256) {
        float4 v = ((const float4*)xr)[i];
        s += v.x * v.x + v.y * v.y + v.z * v.z + v.w * v.w;
    }
    __shared__ float red[8];
    for (int off = 16; off; off >>= 1) s += __shfl_xor_sync(0xffffffffu, s, off);
    if ((threadIdx.x & 31) == 0) red[threadIdx.x >> 5] = s;
    __syncthreads();
    if (threadIdx.x < 8) {
        float t = red[threadIdx.x];
        t += __shfl_xor_sync(0xffu, t, 4);
        t += __shfl_xor_sync(0xffu, t, 2);
        t += __shfl_xor_sync(0xffu, t, 1);
        if (threadIdx.x == 0) red[0] = t;
    }
    __syncthreads();
    float scale = rsqrtf(red[0] * (1.f / D_) + 1.1920929e-7f);
    for (int i = threadIdx.x; i < D_ / 4; i += 256) {
        float4 v = ((const float4*)xr)[i];
        float4 wv = ((const float4*)w)[i];
        v.x *= scale * wv.x; v.y *= scale * wv.y;
        v.z *= scale * wv.z; v.w *= scale * wv.w;
        ((uint2*)(o + (size_t)row * D_))[i] = h4(v);
    }
}

// ---------------------------------------------------------------------------
// fp16 tensor-core GEMM (mid-chunk barrier, fragment-pipelined):
//   C[M, N(ldc)] (op)= A[M,*](lda) @ W[N,*](ldb)^T over K slice [z*kLen, +kLen)
// 128x128 CTA tile, BK=64, 256 threads (8 warps 2x4), warp tile 64x32.
// 3-stage cp.async; barrier placed AFTER pair-0 fragment loads so the next
// chunk's LDGSTS issue overlaps this chunk's MMAs.
// FIX vs r15: prologue must FULLY drain when nCh==1 (cp_wait<1> was a no-op
// with only one group outstanding -> LDSM raced cp.async -> NaN in dt_proj).
// EPI: 0 = store, 1 = atomicAdd (split-K), 3 = softplus(v + bias[n])
// ---------------------------------------------------------------------------
#define GSTG 32768
#define GSM  (3 * GSTG)

template<int EPI>
__global__ void __launch_bounds__(256, 2)
gemm_fp16_kernel(const __half* __restrict__ A, int lda,
                 const __half* __restrict__ Bm, int ldb,
                 const float* __restrict__ aux, float* __restrict__ C,
                 int N, int ldc, int kLen)
{
    extern __shared__ char smem[];
    uint32_t sb = smem_u32(smem);
    int tid = threadIdx.x, wid = tid >> 5, lid = tid & 31;
    int m0 = blockIdx.y * 128, n0 = blockIdx.x * 128;
    int kStart = blockIdx.z * kLen;
    int bRows = N - n0; if (bRows > 128) bRows = 128;
    int wm = (wid >> 2) * 64, wn = (wid & 3) * 32;

    float acc[4][4][4];
#pragma unroll
    for (int i = 0; i < 4; i++)
#pragma unroll
        for (int j = 0; j < 4; j++)
#pragma unroll
            for (int k = 0; k < 4; k++) acc[i][j][k] = 0.f;

    int nCh = kLen / 64;

    auto load_chunk = [&](int s, int k0) {
        uint32_t st = sb + s * GSTG;
#pragma unroll
        for (int p = 0; p < 4; p++) {
            int idx = tid + p * 256;
            int r = idx >> 3, c = idx & 7;
            uint32_t so = sw128((uint32_t)(r * 128 + c * 16));
            cp16(st + so, A + (size_t)(m0 + r) * lda + k0 + c * 8, 16);
        }
#pragma unroll
        for (int p = 0; p < 4; p++) {
            int idx = tid + p * 256;
            int r = idx >> 3, c = idx & 7;
            uint32_t so = sw128((uint32_t)(r * 128 + c * 16));
            int rb = (r < bRows) ? r : (bRows - 1);
            int ok = (r < bRows) ? 16 : 0;
            cp16(st + 16384 + so, Bm + (size_t)(n0 + rb) * ldb + k0 + c * 8, ok);
        }
        cp_commit();
    };

    auto load_af = [&](uint32_t (*af)[4], uint32_t stA, int ks) {
#pragma unroll
        for (int mt = 0; mt < 4; mt++) {
            int row = wm + mt * 16 + (lid & 15);
            int chunk = ks * 2 + (lid >> 4);
            ldsm_x4(af[mt], stA + sw128((uint32_t)(row * 128 + chunk * 16)));
        }
    };
    auto load_bf = [&](uint32_t (*bf)[4], uint32_t stB, int cb) {
#pragma unroll
        for (int nt = 0; nt < 4; nt++) {
            int row = wn + nt * 8 + (lid & 7);
            int chunk = cb + (lid >> 3);
            ldsm_x4(bf[nt], stB + sw128((uint32_t)(row * 128 + chunk * 16)));
        }
    };
    auto mma_step = [&](uint32_t (*af)[4], uint32_t (*bf)[4], int half) {
#pragma unroll
        for (int mt = 0; mt < 4; mt++)
#pragma unroll
            for (int nt = 0; nt < 4; nt++)
                mma_fp16(acc[mt][nt], af[mt], bf[nt] + half * 2);
    };

    // Prologue: fill up to two stages. Stage 0 MUST be fully resident before
    // its LDSMs. With nCh==1 there is only one group in flight, so wait_group<1>
    // would be a no-op -> drain fully in that case.
    load_chunk(0, kStart);
    if (nCh > 1) {
        load_chunk(1, kStart + 64);
        cp_wait<1>();      // stage 0 done; stage 1 may still be in flight
    } else {
        cp_wait<0>();      // single chunk: drain everything
    }
    __syncthreads();

    int stg = 0;
    for (int ch = 0; ch < nCh; ch++) {
        uint32_t stA = sb + stg * GSTG;
        uint32_t stB = stA + 16384;

        uint32_t af0[4][4], af1[4][4], bf[4][4];
        // pair-0 fragments from current stage (resident: guaranteed by the
        // prologue wait for ch==0, by iteration ch-1's cp_wait<0> otherwise)
        load_bf(bf, stB, 0);
        load_af(af0, stA, 0);
        load_af(af1, stA, 1);

        // Mid-chunk barrier: pair-1 reads of the stage being overwritten
        // happened before this barrier (previous iteration, program order).
        if (ch + 1 < nCh) cp_wait<0>();     // next stage fully resident
        __syncthreads();
        if (ch + 2 < nCh) {
            int s2 = stg + 2; if (s2 >= 3) s2 -= 3;
            load_chunk(s2, kStart + (ch + 2) * 64);   // overlaps the MMAs below
        }

        mma_step(af0, bf, 0);        // ks0
        load_af(af0, stA, 2);        // prefetch ks2
        mma_step(af1, bf, 1);        // ks1
        load_bf(bf, stB, 4);         // pair 1
        load_af(af1, stA, 3);        // prefetch ks3
        mma_step(af0, bf, 0);        // ks2
        mma_step(af1, bf, 1);        // ks3

        if (++stg == 3) stg = 0;
    }

    int gid = lid >> 2, tig = lid & 3;
#pragma unroll
    for (int mt = 0; mt < 4; mt++) {
        int r0 = m0 + wm + mt * 16 + gid;
#pragma unroll
        for (int nt = 0; nt < 4; nt++) {
            int cc = n0 + wn + nt * 8 + tig * 2;
            float* a = acc[mt][nt];
#pragma unroll
            for (int half = 0; half < 2; half++) {
                int r = r0 + half * 8;
                float v0 = a[half * 2 + 0], v1 = a[half * 2 + 1];
                size_t o = (size_t)r * ldc + cc;
                if (EPI == 0) {
                    *(float2*)&C[o] = make_float2(v0, v1);
                } else if (EPI == 1) {
                    if (cc < N) { atomicAdd(&C[o], v0); atomicAdd(&C[o + 1], v1); }
                } else {
                    float b0 = aux[cc], b1 = aux[cc + 1];
                    float s0 = v0 + b0, s1 = v1 + b1;
                    s0 = (s0 > 20.f) ? s0 : log1pf(__expf(s0));
                    s1 = (s1 > 20.f) ? s1 : log1pf(__expf(s1));
                    *(float2*)&C[o] = make_float2(s0, s1);
                }
            }
        }
    }
}

// ---------------------------------------------------------------------------
// Depthwise causal conv (width 4) + bias + SiLU -> u (f32, scan) + uh (fp16, GEMM)
// ---------------------------------------------------------------------------
__global__ void conv_silu_kernel(const float* __restrict__ xz,
                                 const float* __restrict__ cw,
                                 const float* __restrict__ cb,
                                 float* __restrict__ u,
                                 __half* __restrict__ uh)
{
    int idx = blockIdx.x * blockDim.x + threadIdx.x;
    if (idx >= MROWS * (DI_ / 4)) return;
    int i4 = idx % (DI_ / 4);
    int bt = idx / (DI_ / 4);
    int t  = bt % T_;
    int i  = i4 * 4;

    float4 w0 = ((const float4*)cw)[i + 0];
    float4 w1 = ((const float4*)cw)[i + 1];
    float4 w2 = ((const float4*)cw)[i + 2];
    float4 w3 = ((const float4*)cw)[i + 3];
    float4 bb = ((const float4*)cb)[i4];

    float4 x3 = (t >= 3) ? *(const float4*)&xz[(size_t)(bt - 3) * (2 * DI_) + i] : make_float4(0, 0, 0, 0);
    float4 x2 = (t >= 2) ? *(const float4*)&xz[(size_t)(bt - 2) * (2 * DI_) + i] : make_float4(0, 0, 0, 0);
    float4 x1 = (t >= 1) ? *(const float4*)&xz[(size_t)(bt - 1) * (2 * DI_) + i] : make_float4(0, 0, 0, 0);
    float4 x0 = *(const float4*)&xz[(size_t)bt * (2 * DI_) + i];

    float4 r;
    r.x = bb.x + w0.x * x3.x + w0.y * x2.x + w0.z * x1.x + w0.w * x0.x;
    r.y = bb.y + w1.x * x3.y + w1.y * x2.y + w1.z * x1.y + w1.w * x0.y;
    r.z = bb.z + w2.x * x3.z + w2.y * x2.z + w2.z * x1.z + w2.w * x0.z;
    r.w = bb.w + w3.x * x3.w + w3.y * x2.w + w3.z * x1.w + w3.w * x0.w;

    r.x = r.x / (1.f + __expf(-r.x));
    r.y = r.y / (1.f + __expf(-r.y));
    r.z = r.z / (1.f + __expf(-r.z));
    r.w = r.w / (1.f + __expf(-r.w));

    ((float4*)u)[idx] = r;
    ((uint2*)uh)[idx] = h4(r);
}

// ---------------------------------------------------------------------------
// Selective scan: smem chunk staging with cp.async double buffering.
// Block = 16 channels x 16 states (256 thr). Chunks of 64 timesteps.
// ---------------------------------------------------------------------------
#define SCH 64
#define NCHK (T_ / SCH)

__global__ void __launch_bounds__(256)
scan_kernel(const float* __restrict__ delta,
            const float* __restrict__ u,
            const float* __restrict__ xdbc,
            const float* __restrict__ xz,
            const float* __restrict__ A_log,
            const float* __restrict__ Dp,
            __half* __restrict__ y)
{
    int b  = blockIdx.x >> 7;
    int ib = blockIdx.x & 127;
    int i0 = ib * 16;
    int tid = threadIdx.x;
    int ci = tid >> 4;
    int s  = tid & 15;
    int i  = i0 + ci;

    __shared__ float sd[2][SCH][16];
    __shared__ float su[2][SCH][16];
    __shared__ float sB[2][SCH][16];
    __shared__ float sC[2][SCH][16];
    __shared__ float sz[2][SCH][16];
    __shared__ float sy[SCH][16];

    float a  = -__expf(A_log[i * DS_ + s]);
    float dp = Dp[i];
    float h  = 0.f;

    int lr = tid >> 2, lc = (tid & 3) * 4;

    auto load_chunk = [&](int stg, int t0) {
        size_t bt = (size_t)(b * T_ + t0 + lr);
        cp16(smem_u32(&sd[stg][lr][lc]), delta + bt * DI_ + i0 + lc, 16);
        cp16(smem_u32(&su[stg][lr][lc]), u + bt * DI_ + i0 + lc, 16);
        cp16(smem_u32(&sB[stg][lr][lc]), xdbc + bt * XDBC_ + R_ + lc, 16);
        cp16(smem_u32(&sC[stg][lr][lc]), xdbc + bt * XDBC_ + R_ + DS_ + lc, 16);
        cp16(smem_u32(&sz[stg][lr][lc]), xz + bt * (2 * DI_) + DI_ + i0 + lc, 16);
        cp_commit();
    };

    load_chunk(0, 0);

    for (int c = 0; c < NCHK; c++) {
        bool hasNext = (c + 1 < NCHK);
        if (hasNext) load_chunk((c + 1) & 1, (c + 1) * SCH);
        if (hasNext) cp_wait<1>(); else cp_wait<0>();
        __syncthreads();

        int stg = c & 1;
#pragma unroll 4
        for (int t = 0; t < SCH; t++) {
            float d  = sd[stg][t][ci];
            float uu = su[stg][t][ci];
            float Bv = sB[stg][t][s];
            float Cv = sC[stg][t][s];
            h = __expf(d * a) * h + (d * uu) * Bv;
            float p = h * Cv;
            p += __shfl_xor_sync(0xffffffffu, p, 8, 16);
            p += __shfl_xor_sync(0xffffffffu, p, 4, 16);
            p += __shfl_xor_sync(0xffffffffu, p, 2, 16);
            p += __shfl_xor_sync(0xffffffffu, p, 1, 16);
            if (s == 0) {
                float z = sz[stg][t][ci];
                sy[t][ci] = (p + uu * dp) * (z / (1.f + __expf(-z)));
            }
        }
        __syncthreads();

        {
            size_t bt = (size_t)(b * T_ + c * SCH + lr);
            float4 v = *(float4*)&sy[lr][lc];
            *(uint2*)(y + bt * DI_ + i0 + lc) = h4(v);
        }
        __syncthreads();
    }
}

// ---------------------------------------------------------------------------
// Launch
// ---------------------------------------------------------------------------
extern "C" void kernel_launch(void* const* d_in, const int* in_sizes, int n_in,
                              void* d_out, int out_size)
{
    const float* x          = (const float*)d_in[0];
    const float* norm_w     = (const float*)d_in[1];
    const float* in_proj_w  = (const float*)d_in[2];
    const float* conv_w     = (const float*)d_in[3];
    const float* conv_b     = (const float*)d_in[4];
    const float* x_proj_w   = (const float*)d_in[5];
    const float* dt_proj_w  = (const float*)d_in[6];
    const float* dt_proj_b  = (const float*)d_in[7];
    const float* A_log      = (const float*)d_in[8];
    const float* D_param    = (const float*)d_in[9];
    const float* out_proj_w = (const float*)d_in[10];
    float* out = (float*)d_out;

    float *xz, *u, *xdbc, *delta;
    __half *xnh, *uh, *yh, *xdbch, *winh, *wouth, *wxph, *wdth;
    cudaGetSymbolAddress((void**)&xz,    g_xz);
    cudaGetSymbolAddress((void**)&u,     g_u);
    cudaGetSymbolAddress((void**)&xdbc,  g_xdbc);
    cudaGetSymbolAddress((void**)&delta, g_delta);
    cudaGetSymbolAddress((void**)&xnh,   g_xnh);
    cudaGetSymbolAddress((void**)&uh,    g_uh);
    cudaGetSymbolAddress((void**)&yh,    g_yh);
    cudaGetSymbolAddress((void**)&xdbch, g_xdbch);
    cudaGetSymbolAddress((void**)&winh,  g_winh);
    cudaGetSymbolAddress((void**)&wouth, g_wouth);
    cudaGetSymbolAddress((void**)&wxph,  g_wxph);
    cudaGetSymbolAddress((void**)&wdth,  g_wdth);

    cudaFuncSetAttribute(gemm_fp16_kernel<0>, cudaFuncAttributeMaxDynamicSharedMemorySize, GSM);
    cudaFuncSetAttribute(gemm_fp16_kernel<1>, cudaFuncAttributeMaxDynamicSharedMemorySize, GSM);
    cudaFuncSetAttribute(gemm_fp16_kernel<3>, cudaFuncAttributeMaxDynamicSharedMemorySize, GSM);

    // #0: convert weights to fp16
    {
        int total = S0_ + S1_ + S2_ + S3_;
        cvt_weights_kernel<<<(total + 255) / 256, 256>>>(
            in_proj_w, winh, out_proj_w, wouth, x_proj_w, wxph, dt_proj_w, wdth);
    }

    // #1: RMSNorm -> xnh
    rmsnorm_kernel<<<MROWS, 256>>>(x, norm_w, xnh);

    // #2: prefill out with residual
    copy_kernel<<<(MROWS * D_ / 4 + 255) / 256, 256>>>(x, out, MROWS * D_ / 4);

    // #3: in_proj: xz[2048,4096] = xn @ W^T   (512 CTAs)  <-- ncu captures this
    gemm_fp16_kernel<0><<<dim3(2 * DI_ / 128, MROWS / 128, 1), 256, GSM>>>(
        xnh, D_, winh, D_, nullptr, xz, 2 * DI_, 2 * DI_, D_);

    // #4: conv + silu -> u (f32) + uh (fp16)
    conv_silu_kernel<<<(MROWS * DI_ / 4 + 255) / 256, 256>>>(xz, conv_w, conv_b, u, uh);

    // #5: x_proj: xdbc = u @ W^T (split-K=8, atomics; 128 CTAs)
    cudaMemsetAsync(xdbc, 0, (size_t)MROWS * XDBC_ * sizeof(float));
    gemm_fp16_kernel<1><<<dim3(1, MROWS / 128, 8), 256, GSM>>>(
        uh, DI_, wxph, DI_, nullptr, xdbc, XDBC_, XDBC_, DI_ / 8);

    // #6: xdbc -> fp16 for dt_proj
    cvt_kernel<<<(MROWS * XDBC_ / 4 + 255) / 256, 256>>>(xdbc, xdbch, MROWS * XDBC_ / 4);

    // #7: dt_proj + softplus: delta[2048,2048] (K=64, single chunk; 256 CTAs)
    gemm_fp16_kernel<3><<<dim3(DI_ / 128, MROWS / 128, 1), 256, GSM>>>(
        xdbch, XDBC_, wdth, R_, dt_proj_b, delta, DI_, DI_, R_);

    // #8: selective scan (fused gate + skip) -> yh
    scan_kernel<<<B_ * (DI_ / 16), 256>>>(delta, u, xdbc, xz, A_log, D_param, yh);

    // #9: out_proj + residual: split-K=4 atomicAdd into prefilled out (512 CTAs)
    gemm_fp16_kernel<1><<<dim3(D_ / 128, MROWS / 128, 4), 256, GSM>>>(
        yh, DI_, wouth, DI_, nullptr, out, D_, D_, DI_ / 4);
}